// round 7
// baseline (speedup 1.0000x reference)
#include <cuda_runtime.h>
#include <cstdint>

#define BIMG 16
#define NBOX 25200
#define ROWST 85
#define NCLS 80
#define KSEL 4096
#define MAXDET 300
#define CHUNK 256
#define CONF_TH 0.6f
#define IOU_TH 0.45f
#define MAXWH 7680.0f
#define NBPI 13            // blocks per image for hist (13*2048 >= 25200)
#define HBINS 4096

// ---- device scratch (zero-initialized at load; self-cleaning across replays) ----
__device__ uint32_t g_mobj[BIMG * NBOX];        // fmap(masked obj)
__device__ uint32_t g_hist[BIMG * HBINS];       // per-image 12-bit histogram
__device__ uint32_t g_bndov[BIMG * NBOX];       // boundary overflow (unused in typical runs)
__device__ uint16_t g_cand[BIMG * KSEL];        // selected row indices (unordered)
__device__ uint64_t g_skey[BIMG * KSEL];        // (fmap(score)<<32)|mobj
__device__ uint32_t g_pay[BIMG * KSEL];         // (n<<12)|ci
__device__ float4   g_boxu[BIMG * KSEL];        // unsorted xyxy per ci
__device__ float    g_clsu[BIMG * KSEL];        // unsorted cls per ci
__device__ float    g_sscore[BIMG * KSEL];      // sorted scores
__device__ uint16_t g_sci[BIMG * KSEL];         // sorted -> ci mapping

__device__ __forceinline__ uint32_t fmap(float f) {
    uint32_t u = __float_as_uint(f);
    return (u & 0x80000000u) ? ~u : (u | 0x80000000u);
}
__device__ __forceinline__ float funmap(uint32_t u) {
    u = (u & 0x80000000u) ? (u & 0x7FFFFFFFu) : ~u;
    return __uint_as_float(u);
}

// ---- K1: mobj + 12-bit histogram (staged loads for MLP) -------------------
__global__ __launch_bounds__(256) void hist_kernel(const float* __restrict__ x) {
    __shared__ uint32_t sh[HBINS];
    const int img = blockIdx.x / NBPI;
    const int blk = blockIdx.x % NBPI;
    const int tid = threadIdx.x;
    for (int b = tid; b < HBINS; b += 256) sh[b] = 0;
    __syncthreads();
    const int base = blk * 2048;
    float objv[8];
    int   nn[8];
    #pragma unroll
    for (int i = 0; i < 8; ++i) {
        nn[i] = base + i * 256 + tid;
        objv[i] = (nn[i] < NBOX) ? __ldg(&x[((size_t)img * NBOX + nn[i]) * ROWST + 4]) : 0.0f;
    }
    #pragma unroll
    for (int i = 0; i < 8; ++i) {
        if (nn[i] < NBOX) {
            float m = objv[i] > CONF_TH ? objv[i] : -1.0f;
            uint32_t mo = fmap(m);
            g_mobj[(size_t)img * NBOX + nn[i]] = mo;
            atomicAdd(&sh[mo >> 20], 1u);
        }
    }
    __syncthreads();
    for (int b = tid; b < HBINS; b += 256) {
        uint32_t c = sh[b];
        if (c) atomicAdd(&g_hist[img * HBINS + b], c);
    }
}

// ---- K2: per-image threshold + partition + boundary radix (fused) ---------
__global__ __launch_bounds__(1024) void select_kernel() {
    __shared__ uint32_t segsum[256];
    __shared__ int sB, sR;
    __shared__ uint64_t sbnd[4096];     // 32 KB boundary keys
    __shared__ uint32_t rhist[256];
    __shared__ uint64_t s_prefix;
    __shared__ int s_rem, s_nc, s_nb;
    const int img = blockIdx.x;
    const int tid = threadIdx.x;
    const int bs = 1024;
    const uint32_t* h = g_hist + img * HBINS;

    if (tid == 0) { s_nc = 0; s_nb = 0; }
    // threshold: bin B and within-bin rank r
    if (tid < 256) {
        uint32_t s = 0;
        #pragma unroll
        for (int j = 0; j < 16; ++j) s += h[4095 - 16 * tid - j];
        segsum[tid] = s;
    }
    __syncthreads();
    if (tid == 0) {
        int cum = 0, B = 0, r = KSEL;
        for (int t = 0; t < 256; ++t) {
            if (cum + (int)segsum[t] >= KSEL) {
                for (int j = 0; j < 16; ++j) {
                    int b = 4095 - 16 * t - j;
                    int c = (int)h[b];
                    if (cum + c >= KSEL) { B = b; r = KSEL - cum; break; }
                    cum += c;
                }
                break;
            }
            cum += (int)segsum[t];
        }
        sB = B; sR = r;
    }
    __syncthreads();
    const int B = sB;

    // partition: definite candidates -> g_cand; boundary-bin keys -> shared
    for (int n = tid; n < NBOX; n += bs) {
        uint32_t mo = g_mobj[(size_t)img * NBOX + n];
        int b = (int)(mo >> 20);
        if (b > B) {
            int p = atomicAdd(&s_nc, 1);
            g_cand[img * KSEL + p] = (uint16_t)n;
        } else if (b == B) {
            int p = atomicAdd(&s_nb, 1);
            uint64_t key = ((uint64_t)mo << 32) | (uint32_t)(~(uint32_t)n);
            if (p < 4096) sbnd[p] = key;
            else g_bndov[(size_t)img * NBOX + (p - 4096)] = (uint32_t)key; // store ~n; mo==B-bin
        }
    }
    __syncthreads();
    const int m = s_nb;
    const int r = sR;

    uint64_t T = 0;
    if (r < m) {
        if (tid == 0) { s_prefix = 0ULL; s_rem = r; }
        __syncthreads();
        for (int d = 7; d >= 0; --d) {
            if (tid < 256) rhist[tid] = 0;
            __syncthreads();
            const int shift = d * 8;
            const uint64_t hmask = (d == 7) ? 0ULL : ~(((uint64_t)1 << ((d + 1) * 8)) - 1ULL);
            const uint64_t pref = s_prefix;
            for (int j = tid; j < m; j += bs) {
                uint64_t k = (j < 4096) ? sbnd[j]
                    : ((sbnd[0] & 0xFFFFFFFF00000000ULL) |
                       (uint64_t)g_bndov[(size_t)img * NBOX + (j - 4096)]);
                if ((k & hmask) == pref) {
                    uint32_t bin = (uint32_t)(k >> shift) & 0xFFu;
                    unsigned am = __activemask();
                    unsigned mm = __match_any_sync(am, bin);
                    int leader = __ffs(mm) - 1;
                    if ((int)(tid & 31) == leader) atomicAdd(&rhist[bin], (uint32_t)__popc(mm));
                }
            }
            __syncthreads();
            if (tid == 0) {
                int rem = s_rem;
                int b = 255;
                for (; b > 0; --b) {
                    int c = (int)rhist[b];
                    if (rem <= c) break;
                    rem -= c;
                }
                s_prefix = pref | ((uint64_t)(uint32_t)b << shift);
                s_rem = rem;
            }
            __syncthreads();
        }
        T = s_prefix;
    }
    __syncthreads();
    for (int j = tid; j < m; j += bs) {
        uint64_t k = (j < 4096) ? sbnd[j]
            : ((sbnd[0] & 0xFFFFFFFF00000000ULL) |
               (uint64_t)g_bndov[(size_t)img * NBOX + (j - 4096)]);
        if (k >= T) {
            int pos = atomicAdd(&s_nc, 1);
            g_cand[img * KSEL + pos] = (uint16_t)(~(uint32_t)k);
        }
    }
    __syncthreads();
    // self-clean histogram for next graph replay
    for (int i = tid; i < HBINS; i += bs) g_hist[img * HBINS + i] = 0;
}

// ---- K3: full-chip score/argmax/box for the 65536 selected rows -----------
__global__ __launch_bounds__(256) void score_kernel(const float* __restrict__ x) {
    const int wid = threadIdx.x >> 5, lane = threadIdx.x & 31;
    const int cidx = blockIdx.x * 8 + wid;
    if (cidx >= BIMG * KSEL) return;
    const int img = cidx >> 12;
    const int ci = cidx & (KSEL - 1);
    const int n = g_cand[cidx];
    const float* R = x + ((size_t)img * NBOX + n) * ROWST;

    float obj = __ldg(&R[4]);
    float v0 = __ldg(&R[5 + lane]);
    float v1 = __ldg(&R[5 + 32 + lane]);
    float v2 = (lane < 16) ? __ldg(&R[5 + 64 + lane]) : -1.0f;
    float best = -1.0f; int bidx = NCLS;
    if (v0 > best) { best = v0; bidx = lane; }
    if (v1 > best) { best = v1; bidx = lane + 32; }
    if (v2 > best) { best = v2; bidx = lane + 64; }
    #pragma unroll
    for (int off = 16; off > 0; off >>= 1) {
        float ov = __shfl_down_sync(0xFFFFFFFFu, best, off);
        int   oi = __shfl_down_sync(0xFFFFFFFFu, bidx, off);
        if (ov > best || (ov == best && oi < bidx)) { best = ov; bidx = oi; }
    }
    if (lane == 0) {
        bool valid = obj > CONF_TH;
        float score = valid ? __fmul_rn(obj, best) : -1.0f;
        uint32_t mo = g_mobj[(size_t)img * NBOX + n];
        g_skey[cidx] = ((uint64_t)fmap(score) << 32) | (uint64_t)mo;
        g_pay[cidx] = ((uint32_t)n << 12) | (uint32_t)ci;
        float cx = __ldg(&R[0]), cy = __ldg(&R[1]), w = __ldg(&R[2]), h = __ldg(&R[3]);
        float hw = __fmul_rn(w, 0.5f), hh = __fmul_rn(h, 0.5f);
        g_boxu[cidx] = make_float4(__fsub_rn(cx, hw), __fsub_rn(cy, hh),
                                   __fadd_rn(cx, hw), __fadd_rn(cy, hh));
        g_clsu[cidx] = (float)bidx;
    }
}

// ---- K4: per-image bitonic sort -> (score, ci) ----------------------------
__global__ __launch_bounds__(1024) void sort_kernel() {
    __shared__ uint64_t sk[KSEL];   // 32 KB
    __shared__ uint32_t sp[KSEL];   // 16 KB
    const int img = blockIdx.x;
    const int tid = threadIdx.x;
    const int bs = blockDim.x;
    for (int i = tid; i < KSEL; i += bs) {
        sk[i] = g_skey[img * KSEL + i];
        sp[i] = g_pay[img * KSEL + i];
    }
    __syncthreads();
    for (unsigned kk = 2; kk <= KSEL; kk <<= 1) {
        for (unsigned j = kk >> 1; j > 0; j >>= 1) {
            if (j >= 16) __syncthreads(); else __syncwarp();
            for (unsigned i = tid; i < KSEL; i += bs) {
                unsigned ixj = i ^ j;
                if (ixj > i) {
                    uint64_t a = sk[i], b = sk[ixj];
                    uint32_t pa = sp[i], pb = sp[ixj];
                    bool gt_i = (a > b) || (a == b && (pa >> 12) < (pb >> 12));
                    bool desc = ((i & kk) == 0);
                    if (gt_i != desc) { sk[i] = b; sk[ixj] = a; sp[i] = pb; sp[ixj] = pa; }
                }
            }
        }
    }
    __syncthreads();
    for (int r = tid; r < KSEL; r += bs) {
        g_sscore[img * KSEL + r] = funmap((uint32_t)(sk[r] >> 32));
        g_sci[img * KSEL + r] = (uint16_t)(sp[r] & (KSEL - 1));
    }
}

// ---- K5: chunked greedy NMS with warp-cooperative resolution --------------
__device__ __forceinline__ int iou_gt(float4 a, float4 b) {
    float lx = fmaxf(a.x, b.x), ly = fmaxf(a.y, b.y);
    float rx = fminf(a.z, b.z), ry = fminf(a.w, b.w);
    float iw = fmaxf(__fsub_rn(rx, lx), 0.0f);
    float ih = fmaxf(__fsub_rn(ry, ly), 0.0f);
    float inter = __fmul_rn(iw, ih);
    float aa = __fmul_rn(__fsub_rn(a.z, a.x), __fsub_rn(a.w, a.y));
    float ab = __fmul_rn(__fsub_rn(b.z, b.x), __fsub_rn(b.w, b.y));
    float denom = __fadd_rn(__fsub_rn(__fadd_rn(aa, ab), inter), 1e-9f);
    return __fdiv_rn(inter, denom) > IOU_TH;
}

__global__ __launch_bounds__(CHUNK) void nms_out_kernel(float* __restrict__ out,
                                                        float* __restrict__ outvalid,
                                                        int write_valid) {
    __shared__ float4 kept[MAXDET];
    __shared__ float4 cob[CHUNK];
    __shared__ float4 corig[CHUNK];
    __shared__ float  cscore[CHUNK];
    __shared__ float  ccls[CHUNK];
    __shared__ uint32_t ssw[8];          // packed cross-chunk suppression bits
    __shared__ uint32_t pm[CHUNK][8];
    __shared__ int    klist[CHUNK];
    __shared__ int    s_k, s_cnt;

    const int img = blockIdx.x;
    const int tid = threadIdx.x;
    const int wid = tid >> 5, lane = tid & 31;
    const float* sc = g_sscore + (size_t)img * KSEL;
    const uint16_t* sci = g_sci + (size_t)img * KSEL;
    if (tid == 0) { s_k = 0; }
    __syncthreads();

    for (int cb = 0; cb < KSEL / CHUNK; ++cb) {
        const int base = cb * CHUNK;
        float s = sc[base + tid];
        int ci = (int)sci[base + tid];
        float4 b = g_boxu[img * KSEL + ci];
        float clsv = g_clsu[img * KSEL + ci];
        float off = __fmul_rn(clsv, MAXWH);
        float4 ob = make_float4(__fadd_rn(b.x, off), __fadd_rn(b.y, off),
                                __fadd_rn(b.z, off), __fadd_rn(b.w, off));
        cob[tid] = ob;
        corig[tid] = b;
        cscore[tid] = s;
        ccls[tid] = clsv;
        int nv = __syncthreads_count(s > 0.0f);
        if (nv == 0) break;

        // suppressed by previously-kept boxes? (packed via ballot)
        int kc = s_k;
        int sup = 0;
        for (int t = 0; t < kc; ++t)
            sup |= iou_gt(ob, kept[t]);
        uint32_t bw = __ballot_sync(0xFFFFFFFFu, sup != 0);
        if (lane == 0) ssw[wid] = bw;

        // pairwise IoU bitmask: row tid vs chunk members
        uint32_t w = 0;
        #pragma unroll 4
        for (int j = 0; j < CHUNK; ++j) {
            w |= (uint32_t)iou_gt(ob, cob[j]) << (j & 31);
            if ((j & 31) == 31) { pm[tid][j >> 5] = w; w = 0; }
        }
        __syncthreads();

        // warp-cooperative serial resolution: 8 lanes hold suppression words
        if (wid == 0) {
            uint32_t Sreg = (lane < 8) ? ssw[lane] : 0u;
            int cnt = 0;
            const int kcur = s_k;
            for (int i = 0; i < nv; ++i) {
                uint32_t wordv = __shfl_sync(0xFFFFFFFFu, Sreg, i >> 5);
                if (!((wordv >> (i & 31)) & 1u)) {
                    if (lane == 0) klist[cnt] = i;
                    cnt++;
                    uint32_t p = (lane < 8) ? pm[i][lane] : 0u;
                    Sreg |= p;
                    if (kcur + cnt >= MAXDET) break;
                }
            }
            if (lane == 0) s_cnt = cnt;
        }
        __syncthreads();

        // append kept + write output rows
        int cnt = s_cnt;
        kc = s_k;
        if (tid < cnt) {
            int i = klist[tid];
            int kpos = kc + tid;
            kept[kpos] = cob[i];
            float4 orig = corig[i];
            float* orow = out + ((size_t)img * MAXDET + kpos) * 6;
            orow[0] = orig.x; orow[1] = orig.y; orow[2] = orig.z; orow[3] = orig.w;
            orow[4] = cscore[i]; orow[5] = ccls[i];
            if (write_valid) outvalid[(size_t)img * MAXDET + kpos] = 1.0f;
        }
        if (tid == 0) s_k = kc + cnt;
        __syncthreads();
        if (s_k >= MAXDET || nv < CHUNK) break;
    }
    __syncthreads();
    int kc = s_k;
    for (int e = tid; e < (MAXDET - kc) * 6; e += blockDim.x)
        out[(size_t)img * MAXDET * 6 + (size_t)kc * 6 + e] = 0.0f;
    if (write_valid)
        for (int r = kc + tid; r < MAXDET; r += blockDim.x)
            outvalid[(size_t)img * MAXDET + r] = 0.0f;
}

extern "C" void kernel_launch(void* const* d_in, const int* in_sizes, int n_in,
                              void* d_out, int out_size) {
    const float* x = (const float*)d_in[0];
    float* out = (float*)d_out;
    int write_valid = (out_size >= BIMG * MAXDET * 7) ? 1 : 0;
    float* outvalid = out + (size_t)BIMG * MAXDET * 6;
    hist_kernel<<<BIMG * NBPI, 256>>>(x);
    select_kernel<<<BIMG, 1024>>>();
    score_kernel<<<(BIMG * KSEL + 7) / 8, 256>>>(x);
    sort_kernel<<<BIMG, 1024>>>();
    nms_out_kernel<<<BIMG, CHUNK>>>(out, outvalid, write_valid);
}

// round 11
// speedup vs baseline: 1.4473x; 1.4473x over previous
#include <cuda_runtime.h>
#include <cstdint>

#define BIMG 16
#define NBOX 25200
#define ROWST 85
#define NCLS 80
#define KSEL 4096
#define PSEL 1024
#define MAXDET 300
#define CHUNK 128
#define NCHUNK (PSEL / CHUNK)
#define CONF_TH 0.6f
#define IOU_T 0.45f
#define MAXWH 7680.0f
#define NBPI 13
#define HBINS 4096

// ---- device scratch (zero-init at load; self-cleaning across replays) ----
__device__ uint32_t g_mobj[BIMG * NBOX];
__device__ uint32_t g_hist[BIMG * HBINS];
__device__ uint32_t g_bndov[BIMG * NBOX];
__device__ uint16_t g_cand[BIMG * KSEL];
__device__ uint64_t g_skey[BIMG * KSEL];     // (fmap(score)<<32)|mobj
__device__ uint32_t g_pay[BIMG * KSEL];      // (n<<12)|ci
__device__ float4   g_boxu[BIMG * KSEL];
__device__ float    g_clsu[BIMG * KSEL];
__device__ float    g_sscore[BIMG * PSEL];   // sorted prefix scores
__device__ uint16_t g_sci[BIMG * PSEL];      // sorted prefix -> ci
__device__ unsigned long long g_selTHi[BIMG];
__device__ uint32_t g_selTLo[BIMG];

__device__ __forceinline__ uint32_t fmap(float f) {
    uint32_t u = __float_as_uint(f);
    return (u & 0x80000000u) ? ~u : (u | 0x80000000u);
}
__device__ __forceinline__ float funmap(uint32_t u) {
    u = (u & 0x80000000u) ? (u & 0x7FFFFFFFu) : ~u;
    return __uint_as_float(u);
}

// ---- K1: mobj + 12-bit histogram --------------------------------------
__global__ __launch_bounds__(256) void hist_kernel(const float* __restrict__ x) {
    __shared__ uint32_t sh[HBINS];
    const int img = blockIdx.x / NBPI;
    const int blk = blockIdx.x % NBPI;
    const int tid = threadIdx.x;
    for (int b = tid; b < HBINS; b += 256) sh[b] = 0;
    __syncthreads();
    const int base = blk * 2048;
    float objv[8];
    int nn[8];
    #pragma unroll
    for (int i = 0; i < 8; ++i) {
        nn[i] = base + i * 256 + tid;
        objv[i] = (nn[i] < NBOX) ? __ldg(&x[((size_t)img * NBOX + nn[i]) * ROWST + 4]) : 0.0f;
    }
    #pragma unroll
    for (int i = 0; i < 8; ++i) {
        if (nn[i] < NBOX) {
            float m = objv[i] > CONF_TH ? objv[i] : -1.0f;
            uint32_t mo = fmap(m);
            g_mobj[(size_t)img * NBOX + nn[i]] = mo;
            atomicAdd(&sh[mo >> 20], 1u);
        }
    }
    __syncthreads();
    for (int b = tid; b < HBINS; b += 256) {
        uint32_t c = sh[b];
        if (c) atomicAdd(&g_hist[img * HBINS + b], c);
    }
}

// ---- K2: threshold + partition + boundary radix (fused, per-image) -----
__global__ __launch_bounds__(1024) void select_kernel() {
    __shared__ uint32_t segsum[256];
    __shared__ int sB, sR;
    __shared__ uint64_t sbnd[4096];
    __shared__ uint32_t rhist[256];
    __shared__ uint64_t s_prefix;
    __shared__ int s_rem, s_nc, s_nb;
    const int img = blockIdx.x;
    const int tid = threadIdx.x;
    const int bs = 1024;
    const uint32_t* h = g_hist + img * HBINS;

    if (tid == 0) { s_nc = 0; s_nb = 0; }
    if (tid < 256) {
        uint32_t s = 0;
        #pragma unroll
        for (int j = 0; j < 16; ++j) s += h[4095 - 16 * tid - j];
        segsum[tid] = s;
    }
    __syncthreads();
    if (tid == 0) {
        int cum = 0, B = 0, r = KSEL;
        for (int t = 0; t < 256; ++t) {
            if (cum + (int)segsum[t] >= KSEL) {
                for (int j = 0; j < 16; ++j) {
                    int b = 4095 - 16 * t - j;
                    int c = (int)h[b];
                    if (cum + c >= KSEL) { B = b; r = KSEL - cum; break; }
                    cum += c;
                }
                break;
            }
            cum += (int)segsum[t];
        }
        sB = B; sR = r;
    }
    __syncthreads();
    const int B = sB;

    for (int n = tid; n < NBOX; n += bs) {
        uint32_t mo = g_mobj[(size_t)img * NBOX + n];
        int b = (int)(mo >> 20);
        if (b > B) {
            int p = atomicAdd(&s_nc, 1);
            g_cand[img * KSEL + p] = (uint16_t)n;
        } else if (b == B) {
            int p = atomicAdd(&s_nb, 1);
            uint64_t key = ((uint64_t)mo << 32) | (uint32_t)(~(uint32_t)n);
            if (p < 4096) sbnd[p] = key;
            else g_bndov[(size_t)img * NBOX + (p - 4096)] = (uint32_t)key;
        }
    }
    __syncthreads();
    const int m = s_nb;
    const int r = sR;

    uint64_t T = 0;
    if (r < m) {
        if (tid == 0) { s_prefix = 0ULL; s_rem = r; }
        __syncthreads();
        for (int d = 7; d >= 0; --d) {
            if (tid < 256) rhist[tid] = 0;
            __syncthreads();
            const int shift = d * 8;
            const uint64_t hmask = (d == 7) ? 0ULL : ~(((uint64_t)1 << ((d + 1) * 8)) - 1ULL);
            const uint64_t pref = s_prefix;
            for (int j = tid; j < m; j += bs) {
                uint64_t k = (j < 4096) ? sbnd[j]
                    : ((sbnd[0] & 0xFFFFFFFF00000000ULL) |
                       (uint64_t)g_bndov[(size_t)img * NBOX + (j - 4096)]);
                if ((k & hmask) == pref) {
                    uint32_t bin = (uint32_t)(k >> shift) & 0xFFu;
                    unsigned am = __activemask();
                    unsigned mm = __match_any_sync(am, bin);
                    int leader = __ffs(mm) - 1;
                    if ((int)(tid & 31) == leader) atomicAdd(&rhist[bin], (uint32_t)__popc(mm));
                }
            }
            __syncthreads();
            if (tid == 0) {
                int rem = s_rem;
                int b = 255;
                for (; b > 0; --b) {
                    int c = (int)rhist[b];
                    if (rem <= c) break;
                    rem -= c;
                }
                s_prefix = pref | ((uint64_t)(uint32_t)b << shift);
                s_rem = rem;
            }
            __syncthreads();
        }
        T = s_prefix;
    }
    __syncthreads();
    for (int j = tid; j < m; j += bs) {
        uint64_t k = (j < 4096) ? sbnd[j]
            : ((sbnd[0] & 0xFFFFFFFF00000000ULL) |
               (uint64_t)g_bndov[(size_t)img * NBOX + (j - 4096)]);
        if (k >= T) {
            int pos = atomicAdd(&s_nc, 1);
            g_cand[img * KSEL + pos] = (uint16_t)(~(uint32_t)k);
        }
    }
    __syncthreads();
    for (int i = tid; i < HBINS; i += bs) g_hist[img * HBINS + i] = 0;
}

// ---- K3: full-chip score/argmax/box for selected rows ------------------
__global__ __launch_bounds__(256) void score_kernel(const float* __restrict__ x) {
    const int wid = threadIdx.x >> 5, lane = threadIdx.x & 31;
    const int cidx = blockIdx.x * 8 + wid;
    if (cidx >= BIMG * KSEL) return;
    const int img = cidx >> 12;
    const int ci = cidx & (KSEL - 1);
    const int n = g_cand[cidx];
    const float* R = x + ((size_t)img * NBOX + n) * ROWST;

    float obj = __ldg(&R[4]);
    float v0 = __ldg(&R[5 + lane]);
    float v1 = __ldg(&R[5 + 32 + lane]);
    float v2 = (lane < 16) ? __ldg(&R[5 + 64 + lane]) : -1.0f;
    float best = -1.0f; int bidx = NCLS;
    if (v0 > best) { best = v0; bidx = lane; }
    if (v1 > best) { best = v1; bidx = lane + 32; }
    if (v2 > best) { best = v2; bidx = lane + 64; }
    #pragma unroll
    for (int off = 16; off > 0; off >>= 1) {
        float ov = __shfl_down_sync(0xFFFFFFFFu, best, off);
        int   oi = __shfl_down_sync(0xFFFFFFFFu, bidx, off);
        if (ov > best || (ov == best && oi < bidx)) { best = ov; bidx = oi; }
    }
    if (lane == 0) {
        bool valid = obj > CONF_TH;
        float score = valid ? __fmul_rn(obj, best) : -1.0f;
        uint32_t mo = g_mobj[(size_t)img * NBOX + n];
        g_skey[cidx] = ((uint64_t)fmap(score) << 32) | (uint64_t)mo;
        g_pay[cidx] = ((uint32_t)n << 12) | (uint32_t)ci;
        float cx = __ldg(&R[0]), cy = __ldg(&R[1]), w = __ldg(&R[2]), h = __ldg(&R[3]);
        float hw = __fmul_rn(w, 0.5f), hh = __fmul_rn(h, 0.5f);
        g_boxu[cidx] = make_float4(__fsub_rn(cx, hw), __fsub_rn(cy, hh),
                                   __fadd_rn(cx, hw), __fadd_rn(cy, hh));
        g_clsu[cidx] = (float)bidx;
    }
}

// ---- K4: exact top-PSEL select (96-bit key, register-resident) + sort --
// Each of 1024 threads stages its 4 (key,pay) pairs in registers once; the
// 12 radix passes run from registers. Shared holds only the compacted
// top-1024 (12 KB) + histogram (1 KB) -> 13.2 KB static, no dynamic smem.
__global__ __launch_bounds__(1024) void sort_kernel() {
    __shared__ uint64_t sk[PSEL];     // 8 KB
    __shared__ uint32_t sp[PSEL];     // 4 KB
    __shared__ uint32_t rhist[256];
    __shared__ uint32_t seg[32];
    __shared__ uint64_t s_prefHi;
    __shared__ uint32_t s_prefLo;
    __shared__ int s_rem, s_cnt;
    const int img = blockIdx.x;
    const int tid = threadIdx.x;

    uint64_t rk[4]; uint32_t rp[4];
    #pragma unroll
    for (int q = 0; q < 4; ++q) {
        int i = tid + q * 1024;
        rk[q] = g_skey[img * KSEL + i];
        rp[q] = g_pay[img * KSEL + i];
    }
    if (tid == 0) { s_prefHi = 0ULL; s_prefLo = 0u; s_rem = PSEL; s_cnt = 0; }
    __syncthreads();

    // 12-pass MSB radix select on unique 96-bit key (skey, ~pay), descending
    for (int d = 11; d >= 0; --d) {
        if (tid < 256) rhist[tid] = 0;
        __syncthreads();
        const uint64_t prefHi = s_prefHi;
        const uint32_t prefLo = s_prefLo;
        #pragma unroll
        for (int q = 0; q < 4; ++q) {
            uint64_t hi = rk[q];
            uint32_t lo = ~rp[q];
            bool match;
            uint32_t bin;
            if (d >= 4) {
                int shift = (d - 4) * 8;
                uint64_t hmask = (d == 11) ? 0ULL : ~((((uint64_t)1) << ((d - 3) * 8)) - 1ULL);
                match = ((hi & hmask) == prefHi);
                bin = (uint32_t)(hi >> shift) & 0xFFu;
            } else {
                int shift = d * 8;
                uint32_t lmask = (d == 3) ? 0u : ~(((1u << ((d + 1) * 8))) - 1u);
                match = (hi == prefHi) && ((lo & lmask) == prefLo);
                bin = (lo >> shift) & 0xFFu;
            }
            if (match) {
                unsigned am = __activemask();
                unsigned mm = __match_any_sync(am, bin);
                int leader = __ffs(mm) - 1;
                if ((int)(tid & 31) == leader) atomicAdd(&rhist[bin], (uint32_t)__popc(mm));
            }
        }
        __syncthreads();
        if (tid < 32) {   // segment sums, descending: seg[t] = bins [255-8t .. 248-8t]
            uint32_t s = 0;
            #pragma unroll
            for (int j = 0; j < 8; ++j) s += rhist[255 - 8 * tid - j];
            seg[tid] = s;
        }
        __syncthreads();
        if (tid == 0) {
            int rem = s_rem;
            int b = 0;
            for (int t = 0; t < 32; ++t) {
                if (rem <= (int)seg[t]) {
                    for (int j = 0; j < 8; ++j) {
                        b = 255 - 8 * t - j;
                        int c = (int)rhist[b];
                        if (rem <= c) break;
                        rem -= c;
                    }
                    break;
                }
                rem -= (int)seg[t];
            }
            if (d >= 4) s_prefHi = s_prefHi | ((uint64_t)(uint32_t)b << ((d - 4) * 8));
            else        s_prefLo = s_prefLo | ((uint32_t)b << (d * 8));
            s_rem = rem;
        }
        __syncthreads();
    }
    const uint64_t THi = s_prefHi;
    const uint32_t TLo = s_prefLo;

    // compact top-PSEL from registers into shared
    #pragma unroll
    for (int q = 0; q < 4; ++q) {
        uint32_t lo = ~rp[q];
        bool sel = (rk[q] > THi) || (rk[q] == THi && lo >= TLo);
        if (sel) {
            int p = atomicAdd(&s_cnt, 1);
            sk[p] = rk[q]; sp[p] = rp[q];
        }
    }
    __syncthreads();

    // bitonic sort PSEL entries: (key desc, pay asc); 1 element per thread
    for (unsigned kk = 2; kk <= PSEL; kk <<= 1) {
        for (unsigned j = kk >> 1; j > 0; j >>= 1) {
            if (j >= 16) __syncthreads(); else __syncwarp();
            unsigned i = tid;
            unsigned ixj = i ^ j;
            if (ixj > i) {
                uint64_t a = sk[i], b = sk[ixj];
                uint32_t pa = sp[i], pb = sp[ixj];
                bool gt_i = (a > b) || (a == b && pa < pb);
                bool desc = ((i & kk) == 0);
                if (gt_i != desc) { sk[i] = b; sk[ixj] = a; sp[i] = pb; sp[ixj] = pa; }
            }
        }
    }
    __syncthreads();
    g_sscore[img * PSEL + tid] = funmap((uint32_t)(sk[tid] >> 32));
    g_sci[img * PSEL + tid] = (uint16_t)(sp[tid] & (KSEL - 1));
    if (tid == 0) { g_selTHi[img] = THi; g_selTLo[img] = TLo; }
}

// ---- K5: chunked greedy NMS with class gating + exact fallback ---------
__device__ __forceinline__ int iou_gt(float4 a, float4 b) {
    float lx = fmaxf(a.x, b.x), ly = fmaxf(a.y, b.y);
    float rx = fminf(a.z, b.z), ry = fminf(a.w, b.w);
    float iw = fmaxf(__fsub_rn(rx, lx), 0.0f);
    float ih = fmaxf(__fsub_rn(ry, ly), 0.0f);
    float inter = __fmul_rn(iw, ih);
    float aa = __fmul_rn(__fsub_rn(a.z, a.x), __fsub_rn(a.w, a.y));
    float ab = __fmul_rn(__fsub_rn(b.z, b.x), __fsub_rn(b.w, b.y));
    float denom = __fadd_rn(__fsub_rn(__fadd_rn(aa, ab), inter), 1e-9f);
    return __fdiv_rn(inter, denom) > IOU_T;
}

__global__ __launch_bounds__(CHUNK) void nms_out_kernel(float* __restrict__ out,
                                                        float* __restrict__ outvalid,
                                                        int write_valid) {
    __shared__ float4 kept[MAXDET];
    __shared__ float  kcls[MAXDET];
    __shared__ float4 cob[CHUNK];
    __shared__ float4 corig[CHUNK];
    __shared__ float  cscore[CHUNK];
    __shared__ float  ccls[CHUNK];
    __shared__ uint32_t ssw[CHUNK / 32];
    __shared__ uint32_t pm[CHUNK][CHUNK / 32];
    __shared__ int klist[CHUNK];
    __shared__ int s_k, s_cnt;
    __shared__ uint32_t sdone[KSEL / 32];
    __shared__ uint64_t rkHi[CHUNK];
    __shared__ uint32_t rkLo[CHUNK];
    __shared__ int      rkI[CHUNK];

    const int img = blockIdx.x;
    const int tid = threadIdx.x;
    const int wid = tid >> 5, lane = tid & 31;
    const float* sc = g_sscore + img * PSEL;
    const uint16_t* sci = g_sci + img * PSEL;
    if (tid == 0) s_k = 0;
    __syncthreads();

    bool truncated = false;
    for (int cb = 0; cb < NCHUNK; ++cb) {
        const int base = cb * CHUNK;
        float s = sc[base + tid];
        int ci = (int)sci[base + tid];
        float4 b = g_boxu[img * KSEL + ci];
        float clsv = g_clsu[img * KSEL + ci];
        float off = __fmul_rn(clsv, MAXWH);
        float4 ob = make_float4(__fadd_rn(b.x, off), __fadd_rn(b.y, off),
                                __fadd_rn(b.z, off), __fadd_rn(b.w, off));
        cob[tid] = ob;
        corig[tid] = b;
        cscore[tid] = s;
        ccls[tid] = clsv;
        int nv = __syncthreads_count(s > 0.0f);
        if (nv == 0) { truncated = true; break; }

        int kc = s_k;
        int sup = 0;
        for (int t = 0; t < kc; ++t)
            if (kcls[t] == clsv && iou_gt(ob, kept[t])) sup = 1;
        uint32_t bw = __ballot_sync(0xFFFFFFFFu, sup != 0);
        if (lane == 0) ssw[wid] = bw;

        uint32_t w = 0;
        for (int j = 0; j < CHUNK; ++j) {
            int bit = (ccls[j] == clsv) ? iou_gt(ob, cob[j]) : 0;
            w |= (uint32_t)bit << (j & 31);
            if ((j & 31) == 31) { pm[tid][j >> 5] = w; w = 0; }
        }
        __syncthreads();

        if (wid == 0) {
            uint32_t Sreg = (lane < CHUNK / 32) ? ssw[lane] : 0u;
            int cnt = 0;
            const int kcur = s_k;
            for (int i = 0; i < nv; ++i) {
                uint32_t wordv = __shfl_sync(0xFFFFFFFFu, Sreg, i >> 5);
                if (!((wordv >> (i & 31)) & 1u)) {
                    if (lane == 0) klist[cnt] = i;
                    cnt++;
                    uint32_t p = (lane < CHUNK / 32) ? pm[i][lane] : 0u;
                    Sreg |= p;
                    if (kcur + cnt >= MAXDET) break;
                }
            }
            if (lane == 0) s_cnt = cnt;
        }
        __syncthreads();

        int cnt = s_cnt;
        kc = s_k;
        if (tid < cnt) {
            int i = klist[tid];
            int kpos = kc + tid;
            kept[kpos] = cob[i];
            kcls[kpos] = ccls[i];
            float4 orig = corig[i];
            float* orow = out + ((size_t)img * MAXDET + kpos) * 6;
            orow[0] = orig.x; orow[1] = orig.y; orow[2] = orig.z; orow[3] = orig.w;
            orow[4] = cscore[i]; orow[5] = ccls[i];
            if (write_valid) outvalid[(size_t)img * MAXDET + kpos] = 1.0f;
        }
        if (tid == 0) s_k = kc + cnt;
        __syncthreads();
        if (s_k >= MAXDET) break;
        if (nv < CHUNK) { truncated = true; break; }
    }
    __syncthreads();

    // exact fallback: continue greedy beyond sorted prefix (dead on typical inputs)
    if (!truncated && s_k < MAXDET) {
        const uint64_t THi = g_selTHi[img];
        const uint32_t TLo = g_selTLo[img];
        for (int i = tid; i < KSEL / 32; i += CHUNK) sdone[i] = 0;
        __syncthreads();
        while (true) {
            uint64_t bHi = 0; uint32_t bLo = 0; int bI = -1;
            for (int i = tid; i < KSEL; i += CHUNK) {
                if ((sdone[i >> 5] >> (i & 31)) & 1u) continue;
                uint64_t hi = g_skey[img * KSEL + i];
                uint32_t lo = ~g_pay[img * KSEL + i];
                if ((hi > THi) || (hi == THi && lo >= TLo)) continue;  // in prefix
                if (bI < 0 || hi > bHi || (hi == bHi && lo > bLo)) { bHi = hi; bLo = lo; bI = i; }
            }
            rkHi[tid] = bHi; rkLo[tid] = bLo; rkI[tid] = bI;
            __syncthreads();
            for (int off2 = CHUNK / 2; off2 > 0; off2 >>= 1) {
                if (tid < off2) {
                    bool better = rkI[tid + off2] >= 0 &&
                        (rkI[tid] < 0 || rkHi[tid + off2] > rkHi[tid] ||
                         (rkHi[tid + off2] == rkHi[tid] && rkLo[tid + off2] > rkLo[tid]));
                    if (better) { rkHi[tid] = rkHi[tid + off2]; rkLo[tid] = rkLo[tid + off2]; rkI[tid] = rkI[tid + off2]; }
                }
                __syncthreads();
            }
            int bi = rkI[0];
            if (bi < 0) break;
            float s = funmap((uint32_t)(rkHi[0] >> 32));
            if (!(s > 0.0f)) break;
            uint32_t pay = ~rkLo[0];
            int ci = (int)(pay & (KSEL - 1));
            float4 b = g_boxu[img * KSEL + ci];
            float clsv = g_clsu[img * KSEL + ci];
            float off = __fmul_rn(clsv, MAXWH);
            float4 ob = make_float4(__fadd_rn(b.x, off), __fadd_rn(b.y, off),
                                    __fadd_rn(b.z, off), __fadd_rn(b.w, off));
            int sup = 0;
            for (int t = tid; t < s_k; t += CHUNK)
                if (kcls[t] == clsv && iou_gt(ob, kept[t])) sup = 1;
            int any = __syncthreads_or(sup);
            if (!any) {
                if (tid == 0) {
                    int k = s_k;
                    kept[k] = ob; kcls[k] = clsv;
                    float* orow = out + ((size_t)img * MAXDET + k) * 6;
                    orow[0] = b.x; orow[1] = b.y; orow[2] = b.z; orow[3] = b.w;
                    orow[4] = s; orow[5] = clsv;
                    if (write_valid) outvalid[(size_t)img * MAXDET + k] = 1.0f;
                    s_k = k + 1;
                }
            }
            __syncthreads();
            if (s_k >= MAXDET) break;
            if (tid == 0) sdone[bi >> 5] |= 1u << (bi & 31);
            __syncthreads();
        }
    }
    __syncthreads();
    int kc = s_k;
    for (int e = tid; e < (MAXDET - kc) * 6; e += blockDim.x)
        out[(size_t)img * MAXDET * 6 + (size_t)kc * 6 + e] = 0.0f;
    if (write_valid)
        for (int r = kc + tid; r < MAXDET; r += blockDim.x)
            outvalid[(size_t)img * MAXDET + r] = 0.0f;
}

extern "C" void kernel_launch(void* const* d_in, const int* in_sizes, int n_in,
                              void* d_out, int out_size) {
    const float* x = (const float*)d_in[0];
    float* out = (float*)d_out;
    int write_valid = (out_size >= BIMG * MAXDET * 7) ? 1 : 0;
    float* outvalid = out + (size_t)BIMG * MAXDET * 6;
    hist_kernel<<<BIMG * NBPI, 256>>>(x);
    select_kernel<<<BIMG, 1024>>>();
    score_kernel<<<(BIMG * KSEL + 7) / 8, 256>>>(x);
    sort_kernel<<<BIMG, 1024>>>();
    nms_out_kernel<<<BIMG, CHUNK>>>(out, outvalid, write_valid);
}

// round 12
// speedup vs baseline: 1.7536x; 1.2117x over previous
#include <cuda_runtime.h>
#include <cstdint>

#define BIMG 16
#define NBOX 25200
#define ROWST 85
#define NCLS 80
#define KSEL 4096
#define PSEL 1024
#define MAXDET 300
#define CHUNK 128
#define NCHUNK (PSEL / CHUNK)
#define CONF_TH 0.6f
#define IOU_T 0.45f
#define MAXWH 7680.0f
#define NBPI 13
#define HBINS 4096
#define LO_OBJ 0xBF19999Au   /* fmap(0.6f) */
#define LO_SCR 0xBF000000u   /* fmap(0.5f), 2^11-aligned */

// ---- device scratch (zero-init at load; self-cleaning across replays) ----
__device__ uint32_t g_mobj[BIMG * NBOX];
__device__ uint32_t g_hist[BIMG * HBINS];
__device__ uint32_t g_bndov[BIMG * NBOX];
__device__ uint16_t g_cand[BIMG * KSEL];
__device__ uint64_t g_skey[BIMG * KSEL];     // (fmap(score)<<32)|mobj
__device__ uint32_t g_pay[BIMG * KSEL];      // (n<<12)|ci
__device__ float4   g_boxu[BIMG * KSEL];
__device__ float    g_clsu[BIMG * KSEL];

__device__ __forceinline__ uint32_t fmap(float f) {
    uint32_t u = __float_as_uint(f);
    return (u & 0x80000000u) ? ~u : (u | 0x80000000u);
}
__device__ __forceinline__ float funmap(uint32_t u) {
    u = (u & 0x80000000u) ? (u & 0x7FFFFFFFu) : ~u;
    return __uint_as_float(u);
}
// order-preserving fine bin for masked-obj keys (valid keys in (LO_OBJ, fmap(1.0)])
__device__ __forceinline__ uint32_t obj_bin(uint32_t mo) {
    if (mo <= LO_OBJ) return 0u;
    uint32_t b = (mo - LO_OBJ) >> 11;
    return b > 4095u ? 4095u : b;
}

// ---- K1: mobj + fine histogram ----------------------------------------
__global__ __launch_bounds__(256) void hist_kernel(const float* __restrict__ x) {
    __shared__ uint32_t sh[HBINS];
    const int img = blockIdx.x / NBPI;
    const int blk = blockIdx.x % NBPI;
    const int tid = threadIdx.x;
    for (int b = tid; b < HBINS; b += 256) sh[b] = 0;
    __syncthreads();
    const int base = blk * 2048;
    float objv[8];
    int nn[8];
    #pragma unroll
    for (int i = 0; i < 8; ++i) {
        nn[i] = base + i * 256 + tid;
        objv[i] = (nn[i] < NBOX) ? __ldg(&x[((size_t)img * NBOX + nn[i]) * ROWST + 4]) : 0.0f;
    }
    #pragma unroll
    for (int i = 0; i < 8; ++i) {
        if (nn[i] < NBOX) {
            float m = objv[i] > CONF_TH ? objv[i] : -1.0f;
            uint32_t mo = fmap(m);
            g_mobj[(size_t)img * NBOX + nn[i]] = mo;
            atomicAdd(&sh[obj_bin(mo)], 1u);
        }
    }
    __syncthreads();
    for (int b = tid; b < HBINS; b += 256) {
        uint32_t c = sh[b];
        if (c) atomicAdd(&g_hist[img * HBINS + b], c);
    }
}

// ---- K2: threshold + partition + boundary radix (fused, per-image) -----
__global__ __launch_bounds__(1024) void select_kernel() {
    __shared__ uint32_t segsum[256];
    __shared__ int sB, sR;
    __shared__ uint64_t sbnd[4096];
    __shared__ uint32_t rhist[256];
    __shared__ uint64_t s_prefix;
    __shared__ int s_rem, s_nc, s_nb;
    const int img = blockIdx.x;
    const int tid = threadIdx.x;
    const int bs = 1024;
    const uint32_t* h = g_hist + img * HBINS;

    if (tid == 0) { s_nc = 0; s_nb = 0; }
    if (tid < 256) {
        uint32_t s = 0;
        #pragma unroll
        for (int j = 0; j < 16; ++j) s += h[4095 - 16 * tid - j];
        segsum[tid] = s;
    }
    __syncthreads();
    if (tid == 0) {
        int cum = 0, B = 0, r = KSEL;
        for (int t = 0; t < 256; ++t) {
            if (cum + (int)segsum[t] >= KSEL) {
                for (int j = 0; j < 16; ++j) {
                    int b = 4095 - 16 * t - j;
                    int c = (int)h[b];
                    if (cum + c >= KSEL) { B = b; r = KSEL - cum; break; }
                    cum += c;
                }
                break;
            }
            cum += (int)segsum[t];
        }
        sB = B; sR = r;
    }
    __syncthreads();
    const int B = sB;

    for (int n = tid; n < NBOX; n += bs) {
        uint32_t mo = g_mobj[(size_t)img * NBOX + n];
        int b = (int)obj_bin(mo);
        if (b > B) {
            int p = atomicAdd(&s_nc, 1);
            g_cand[img * KSEL + p] = (uint16_t)n;
        } else if (b == B) {
            int p = atomicAdd(&s_nb, 1);
            uint64_t key = ((uint64_t)mo << 32) | (uint32_t)(~(uint32_t)n);
            if (p < 4096) sbnd[p] = key;
            else g_bndov[(size_t)img * NBOX + (p - 4096)] = (uint32_t)key;
        }
    }
    __syncthreads();
    const int m = s_nb;
    const int r = sR;

    uint64_t T = 0;
    if (r < m) {
        if (tid == 0) { s_prefix = 0ULL; s_rem = r; }
        __syncthreads();
        for (int d = 7; d >= 0; --d) {
            if (tid < 256) rhist[tid] = 0;
            __syncthreads();
            const int shift = d * 8;
            const uint64_t hmask = (d == 7) ? 0ULL : ~(((uint64_t)1 << ((d + 1) * 8)) - 1ULL);
            const uint64_t pref = s_prefix;
            for (int j = tid; j < m; j += bs) {
                uint64_t k = (j < 4096) ? sbnd[j]
                    : ((sbnd[0] & 0xFFFFFFFF00000000ULL) |
                       (uint64_t)g_bndov[(size_t)img * NBOX + (j - 4096)]);
                if ((k & hmask) == pref) {
                    uint32_t bin = (uint32_t)(k >> shift) & 0xFFu;
                    unsigned am = __activemask();
                    unsigned mm = __match_any_sync(am, bin);
                    int leader = __ffs(mm) - 1;
                    if ((int)(tid & 31) == leader) atomicAdd(&rhist[bin], (uint32_t)__popc(mm));
                }
            }
            __syncthreads();
            if (tid == 0) {
                int rem = s_rem;
                int b = 255;
                for (; b > 0; --b) {
                    int c = (int)rhist[b];
                    if (rem <= c) break;
                    rem -= c;
                }
                s_prefix = pref | ((uint64_t)(uint32_t)b << shift);
                s_rem = rem;
            }
            __syncthreads();
        }
        T = s_prefix;
    }
    __syncthreads();
    for (int j = tid; j < m; j += bs) {
        uint64_t k = (j < 4096) ? sbnd[j]
            : ((sbnd[0] & 0xFFFFFFFF00000000ULL) |
               (uint64_t)g_bndov[(size_t)img * NBOX + (j - 4096)]);
        if (k >= T) {
            int pos = atomicAdd(&s_nc, 1);
            g_cand[img * KSEL + pos] = (uint16_t)(~(uint32_t)k);
        }
    }
    __syncthreads();
    for (int i = tid; i < HBINS; i += bs) g_hist[img * HBINS + i] = 0;
}

// ---- K3: full-chip score/argmax/box for selected rows ------------------
__global__ __launch_bounds__(256) void score_kernel(const float* __restrict__ x) {
    const int wid = threadIdx.x >> 5, lane = threadIdx.x & 31;
    const int cidx = blockIdx.x * 8 + wid;
    if (cidx >= BIMG * KSEL) return;
    const int img = cidx >> 12;
    const int ci = cidx & (KSEL - 1);
    const int n = g_cand[cidx];
    const float* R = x + ((size_t)img * NBOX + n) * ROWST;

    float obj = __ldg(&R[4]);
    float v0 = __ldg(&R[5 + lane]);
    float v1 = __ldg(&R[5 + 32 + lane]);
    float v2 = (lane < 16) ? __ldg(&R[5 + 64 + lane]) : -1.0f;
    float best = -1.0f; int bidx = NCLS;
    if (v0 > best) { best = v0; bidx = lane; }
    if (v1 > best) { best = v1; bidx = lane + 32; }
    if (v2 > best) { best = v2; bidx = lane + 64; }
    #pragma unroll
    for (int off = 16; off > 0; off >>= 1) {
        float ov = __shfl_down_sync(0xFFFFFFFFu, best, off);
        int   oi = __shfl_down_sync(0xFFFFFFFFu, bidx, off);
        if (ov > best || (ov == best && oi < bidx)) { best = ov; bidx = oi; }
    }
    if (lane == 0) {
        bool valid = obj > CONF_TH;
        float score = valid ? __fmul_rn(obj, best) : -1.0f;
        uint32_t mo = g_mobj[(size_t)img * NBOX + n];
        g_skey[cidx] = ((uint64_t)fmap(score) << 32) | (uint64_t)mo;
        g_pay[cidx] = ((uint32_t)n << 12) | (uint32_t)ci;
        float cx = __ldg(&R[0]), cy = __ldg(&R[1]), w = __ldg(&R[2]), h = __ldg(&R[3]);
        float hw = __fmul_rn(w, 0.5f), hh = __fmul_rn(h, 0.5f);
        g_boxu[cidx] = make_float4(__fsub_rn(cx, hw), __fsub_rn(cy, hh),
                                   __fadd_rn(cx, hw), __fadd_rn(cy, hh));
        g_clsu[cidx] = (float)bidx;
    }
}

// digit p of the 96-bit key (H=fmap(score), M=mobj, L=~pay), MSD order.
// p0 is a range-accelerated bin (order-preserving); p1..p8 cover all bits.
__device__ __forceinline__ uint32_t sn_digit(uint64_t k, uint32_t pay, int p) {
    uint32_t H = (uint32_t)(k >> 32);
    uint32_t M = (uint32_t)k;
    uint32_t L = ~pay;
    switch (p) {
    case 0: { if (H <= LO_SCR) return 0u;
              uint32_t b = (H - LO_SCR) >> 11; return b > 4095u ? 4095u : b; }
    case 1: return H >> 20;
    case 2: return (H >> 8) & 0xFFFu;
    case 3: return ((H & 0xFFu) << 4) | (M >> 28);
    case 4: return (M >> 16) & 0xFFFu;
    case 5: return (M >> 4) & 0xFFFu;
    case 6: return ((M & 0xFu) << 8) | (L >> 24);
    case 7: return (L >> 12) & 0xFFFu;
    default: return L & 0xFFFu;
    }
}
__device__ __forceinline__ int key_gt(uint32_t aH, uint32_t aM, uint32_t aL,
                                      uint32_t bH2, uint32_t bM2, uint32_t bL2) {
    if (aH != bH2) return aH > bH2;
    if (aM != bM2) return aM > bM2;
    return aL > bL2;
}

// ---- K4: fused exact top-PSEL select + sort + NMS (one kernel) ---------
__device__ __forceinline__ int iou_gt(float4 a, float4 b) {
    float lx = fmaxf(a.x, b.x), ly = fmaxf(a.y, b.y);
    float rx = fminf(a.z, b.z), ry = fminf(a.w, b.w);
    float iw = fmaxf(__fsub_rn(rx, lx), 0.0f);
    float ih = fmaxf(__fsub_rn(ry, ly), 0.0f);
    float inter = __fmul_rn(iw, ih);
    float aa = __fmul_rn(__fsub_rn(a.z, a.x), __fsub_rn(a.w, a.y));
    float ab = __fmul_rn(__fsub_rn(b.z, b.x), __fsub_rn(b.w, b.y));
    float denom = __fadd_rn(__fsub_rn(__fadd_rn(aa, ab), inter), 1e-9f);
    return __fdiv_rn(inter, denom) > IOU_T;
}

__global__ __launch_bounds__(1024) void sortnms_kernel(float* __restrict__ out,
                                                       float* __restrict__ outvalid,
                                                       int write_valid) {
    __shared__ __align__(16) uint8_t scratch[16384];   // phase A: hist; phase B: kept/kcls/pm16
    __shared__ uint64_t sk[PSEL];
    __shared__ uint32_t sp[PSEL];
    __shared__ uint32_t segsum[256];
    __shared__ uint32_t bHh[256], bMm[256], bLl[256];
    __shared__ int bSel[256];
    __shared__ int sD, sRem, sMb, sBcnt, sCnt;
    __shared__ uint32_t rwH[32], rwM[32], rwL[32];
    __shared__ uint32_t sbH, sbM, sbL;
    __shared__ float4 cob[CHUNK], corig[CHUNK];
    __shared__ float cscore[CHUNK], ccls[CHUNK];
    __shared__ int klist[CHUNK];
    __shared__ uint32_t ssw[4];
    __shared__ int s_k, s_cnt2;

    const int img = blockIdx.x;
    const int tid = threadIdx.x;
    const int wid = tid >> 5, lane = tid & 31;
    uint32_t* hist = (uint32_t*)scratch;

    // ---- Phase A: exact top-PSEL selection, keys register-resident ----
    uint64_t rk[4]; uint32_t rp[4];
    bool act[4], sel[4];
    int bpos[4];
    #pragma unroll
    for (int q = 0; q < 4; ++q) {
        int i = tid + q * 1024;
        rk[q] = g_skey[img * KSEL + i];
        rp[q] = g_pay[img * KSEL + i];
        act[q] = true; sel[q] = false; bpos[q] = -1;
    }
    if (tid == 0) { sRem = PSEL; sBcnt = 0; sCnt = 0; }
    __syncthreads();

    bool done = false;
    for (int p = 0; p < 9 && !done; ++p) {
        for (int i = tid; i < 4096; i += 1024) hist[i] = 0;
        __syncthreads();
        #pragma unroll
        for (int q = 0; q < 4; ++q) {
            if (act[q]) {
                uint32_t d = sn_digit(rk[q], rp[q], p);
                unsigned am = __activemask();
                unsigned mm = __match_any_sync(am, d);
                int leader = __ffs(mm) - 1;
                if ((int)(tid & 31) == leader) atomicAdd(&hist[d], (uint32_t)__popc(mm));
            }
        }
        __syncthreads();
        if (tid < 256) {
            uint32_t s = 0;
            #pragma unroll
            for (int j = 0; j < 16; ++j) s += hist[4095 - 16 * tid - j];
            segsum[tid] = s;
        }
        __syncthreads();
        if (tid == 0) {
            int rem = sRem;
            int cum = 0, D = 0, r2 = rem;
            for (int t = 0; t < 256; ++t) {
                if (cum + (int)segsum[t] >= rem) {
                    for (int j = 0; j < 16; ++j) {
                        int b = 4095 - 16 * t - j;
                        int c = (int)hist[b];
                        if (cum + c >= rem) { D = b; r2 = rem - cum; break; }
                        cum += c;
                    }
                    break;
                }
                cum += (int)segsum[t];
            }
            sD = D; sRem = r2; sMb = (int)hist[D];
        }
        __syncthreads();
        const uint32_t D = (uint32_t)sD;
        const int rem2 = sRem, mb = sMb;
        #pragma unroll
        for (int q = 0; q < 4; ++q) {
            if (act[q]) {
                uint32_t d = sn_digit(rk[q], rp[q], p);
                if (d > D) { sel[q] = true; act[q] = false; }
                else if (d < D) act[q] = false;
            }
        }
        if (rem2 == mb) {
            #pragma unroll
            for (int q = 0; q < 4; ++q) if (act[q]) { sel[q] = true; act[q] = false; }
            done = true;
        } else if (mb <= 256) {
            #pragma unroll
            for (int q = 0; q < 4; ++q) {
                if (act[q]) {
                    int pos = atomicAdd(&sBcnt, 1);
                    bHh[pos] = (uint32_t)(rk[q] >> 32);
                    bMm[pos] = (uint32_t)rk[q];
                    bLl[pos] = ~rp[q];
                    bpos[q] = pos;
                }
            }
            __syncthreads();
            int m = sBcnt;
            if (tid < m) {
                uint32_t mH = bHh[tid], mM = bMm[tid], mL = bLl[tid];
                int rank = 0;
                for (int j = 0; j < m; ++j)
                    rank += key_gt(bHh[j], bMm[j], bLl[j], mH, mM, mL);
                bSel[tid] = (rank < rem2);
            }
            __syncthreads();
            #pragma unroll
            for (int q = 0; q < 4; ++q)
                if (act[q]) { sel[q] = (bSel[bpos[q]] != 0); act[q] = false; }
            done = true;
        }
        __syncthreads();
    }

    // compact selected PSEL entries, then bitonic sort (key desc, pay asc)
    #pragma unroll
    for (int q = 0; q < 4; ++q) {
        if (sel[q]) {
            int p = atomicAdd(&sCnt, 1);
            sk[p] = rk[q]; sp[p] = rp[q];
        }
    }
    __syncthreads();
    for (unsigned kk = 2; kk <= PSEL; kk <<= 1) {
        for (unsigned j = kk >> 1; j > 0; j >>= 1) {
            if (j >= 16) __syncthreads(); else __syncwarp();
            unsigned i = tid;
            unsigned ixj = i ^ j;
            if (ixj > i) {
                uint64_t a = sk[i], b = sk[ixj];
                uint32_t pa = sp[i], pb = sp[ixj];
                bool gt_i = (a > b) || (a == b && pa < pb);
                bool desc = ((i & kk) == 0);
                if (gt_i != desc) { sk[i] = b; sk[ixj] = a; sp[i] = pb; sp[ixj] = pa; }
            }
        }
    }
    __syncthreads();

    // ---- Phase B: chunked greedy NMS (scratch realiased) ----
    float4* kept = (float4*)scratch;                         // 4800 B
    float*  kcls = (float*)(scratch + 4800);                 // 1200 B
    uint16_t (*pm16)[8] = (uint16_t(*)[8])(scratch + 6016);  // 2048 B
    if (tid == 0) s_k = 0;
    __syncthreads();

    bool truncated = false;
    for (int cb = 0; cb < NCHUNK; ++cb) {
        const int base = cb * CHUNK;
        float s = -1.0f;
        if (tid < CHUNK) {
            s = funmap((uint32_t)(sk[base + tid] >> 32));
            int ci = (int)(sp[base + tid] & (KSEL - 1));
            float4 b = g_boxu[img * KSEL + ci];
            float clsv = g_clsu[img * KSEL + ci];
            float off = __fmul_rn(clsv, MAXWH);
            float4 ob = make_float4(__fadd_rn(b.x, off), __fadd_rn(b.y, off),
                                    __fadd_rn(b.z, off), __fadd_rn(b.w, off));
            cob[tid] = ob;
            corig[tid] = b;
            cscore[tid] = s;
            ccls[tid] = clsv;
        }
        int nv = __syncthreads_count(tid < CHUNK && s > 0.0f);
        if (nv == 0) { truncated = true; break; }

        // suppressed by previously-kept (class-gated)?
        int kc = s_k;
        if (tid < CHUNK) {
            float4 ob = cob[tid];
            float clsv = ccls[tid];
            int sup = 0;
            for (int t = 0; t < kc; ++t)
                if (kcls[t] == clsv && iou_gt(ob, kept[t])) sup = 1;
            uint32_t bw = __ballot_sync(0xFFFFFFFFu, sup != 0);
            if (lane == 0) ssw[wid] = bw;
        }
        // pairwise (row, 16-j slice) per thread
        {
            int row = tid & (CHUNK - 1);
            int part = tid >> 7;            // 0..7
            float4 ob = cob[row];
            float clsv = ccls[row];
            uint32_t w = 0;
            int j0 = part * 16;
            #pragma unroll
            for (int jj = 0; jj < 16; ++jj) {
                int j = j0 + jj;
                int bit = (ccls[j] == clsv) ? iou_gt(ob, cob[j]) : 0;
                w |= (uint32_t)bit << jj;
            }
            pm16[row][part] = (uint16_t)w;
        }
        __syncthreads();

        if (wid == 0) {
            uint32_t Sreg = (lane < 4) ? ssw[lane] : 0u;
            int cnt = 0;
            const int kcur = s_k;
            for (int i = 0; i < nv; ++i) {
                uint32_t wordv = __shfl_sync(0xFFFFFFFFu, Sreg, i >> 5);
                if (!((wordv >> (i & 31)) & 1u)) {
                    if (lane == 0) klist[cnt] = i;
                    cnt++;
                    uint32_t p = (lane < 4)
                        ? ((uint32_t)pm16[i][2 * lane] | ((uint32_t)pm16[i][2 * lane + 1] << 16))
                        : 0u;
                    Sreg |= p;
                    if (kcur + cnt >= MAXDET) break;
                }
            }
            if (lane == 0) s_cnt2 = cnt;
        }
        __syncthreads();

        int cnt = s_cnt2;
        kc = s_k;
        if (tid < cnt) {
            int i = klist[tid];
            int kpos = kc + tid;
            kept[kpos] = cob[i];
            kcls[kpos] = ccls[i];
            float4 orig = corig[i];
            float* orow = out + ((size_t)img * MAXDET + kpos) * 6;
            orow[0] = orig.x; orow[1] = orig.y; orow[2] = orig.z; orow[3] = orig.w;
            orow[4] = cscore[i]; orow[5] = ccls[i];
            if (write_valid) outvalid[(size_t)img * MAXDET + kpos] = 1.0f;
        }
        if (tid == 0) s_k = kc + cnt;
        __syncthreads();
        if (s_k >= MAXDET) break;
        if (nv < CHUNK) { truncated = true; break; }
    }
    __syncthreads();

    // exact fallback beyond the prefix (register-resident; dead on typical data)
    if (!truncated && s_k < MAXDET) {
        bool used[4];
        #pragma unroll
        for (int q = 0; q < 4; ++q) used[q] = sel[q];
        while (true) {
            uint32_t hH = 0, hM = 0, hL = 0;
            #pragma unroll
            for (int q = 0; q < 4; ++q) {
                if (!used[q]) {
                    uint32_t H = (uint32_t)(rk[q] >> 32), M = (uint32_t)rk[q], L = ~rp[q];
                    if (key_gt(H, M, L, hH, hM, hL)) { hH = H; hM = M; hL = L; }
                }
            }
            #pragma unroll
            for (int o = 16; o > 0; o >>= 1) {
                uint32_t oH = __shfl_down_sync(0xFFFFFFFFu, hH, o);
                uint32_t oM = __shfl_down_sync(0xFFFFFFFFu, hM, o);
                uint32_t oL = __shfl_down_sync(0xFFFFFFFFu, hL, o);
                if (key_gt(oH, oM, oL, hH, hM, hL)) { hH = oH; hM = oM; hL = oL; }
            }
            if (lane == 0) { rwH[wid] = hH; rwM[wid] = hM; rwL[wid] = hL; }
            __syncthreads();
            if (wid == 0) {
                hH = rwH[lane]; hM = rwM[lane]; hL = rwL[lane];
                #pragma unroll
                for (int o = 16; o > 0; o >>= 1) {
                    uint32_t oH = __shfl_down_sync(0xFFFFFFFFu, hH, o);
                    uint32_t oM = __shfl_down_sync(0xFFFFFFFFu, hM, o);
                    uint32_t oL = __shfl_down_sync(0xFFFFFFFFu, hL, o);
                    if (key_gt(oH, oM, oL, hH, hM, hL)) { hH = oH; hM = oM; hL = oL; }
                }
                if (lane == 0) { sbH = hH; sbM = hM; sbL = hL; }
            }
            __syncthreads();
            uint32_t BH = sbH, BM = sbM, BL = sbL;
            float s = funmap(BH);
            if (!(s > 0.0f)) break;
            int ci = (int)((~BL) & (KSEL - 1));
            float4 b = g_boxu[img * KSEL + ci];
            float clsv = g_clsu[img * KSEL + ci];
            float off = __fmul_rn(clsv, MAXWH);
            float4 ob = make_float4(__fadd_rn(b.x, off), __fadd_rn(b.y, off),
                                    __fadd_rn(b.z, off), __fadd_rn(b.w, off));
            int sup = 0;
            for (int t = tid; t < s_k; t += 1024)
                if (kcls[t] == clsv && iou_gt(ob, kept[t])) sup = 1;
            int any = __syncthreads_or(sup);
            if (!any && tid == 0) {
                int k = s_k;
                kept[k] = ob; kcls[k] = clsv;
                float* orow = out + ((size_t)img * MAXDET + k) * 6;
                orow[0] = b.x; orow[1] = b.y; orow[2] = b.z; orow[3] = b.w;
                orow[4] = s; orow[5] = clsv;
                if (write_valid) outvalid[(size_t)img * MAXDET + k] = 1.0f;
                s_k = k + 1;
            }
            #pragma unroll
            for (int q = 0; q < 4; ++q)
                if (!used[q] && (uint32_t)(rk[q] >> 32) == BH &&
                    (uint32_t)rk[q] == BM && (~rp[q]) == BL) used[q] = true;
            __syncthreads();
            if (s_k >= MAXDET) break;
        }
    }
    __syncthreads();
    int kc = s_k;
    for (int e = tid; e < (MAXDET - kc) * 6; e += 1024)
        out[(size_t)img * MAXDET * 6 + (size_t)kc * 6 + e] = 0.0f;
    if (write_valid)
        for (int r = kc + tid; r < MAXDET; r += 1024)
            outvalid[(size_t)img * MAXDET + r] = 0.0f;
}

extern "C" void kernel_launch(void* const* d_in, const int* in_sizes, int n_in,
                              void* d_out, int out_size) {
    const float* x = (const float*)d_in[0];
    float* out = (float*)d_out;
    int write_valid = (out_size >= BIMG * MAXDET * 7) ? 1 : 0;
    float* outvalid = out + (size_t)BIMG * MAXDET * 6;
    hist_kernel<<<BIMG * NBPI, 256>>>(x);
    select_kernel<<<BIMG, 1024>>>();
    score_kernel<<<(BIMG * KSEL + 7) / 8, 256>>>(x);
    sortnms_kernel<<<BIMG, 1024>>>(out, outvalid, write_valid);
}

// round 15
// speedup vs baseline: 3.1532x; 1.7981x over previous
#include <cuda_runtime.h>
#include <cstdint>

#define BIMG 16
#define NBOX 25200
#define ROWST 85
#define NCLS 80
#define KSEL 4096
#define PSEL 1024
#define MAXDET 300
#define CHUNK 128
#define NCHUNK (PSEL / CHUNK)
#define CONF_TH 0.6f
#define IOU_T 0.45f
#define MAXWH 7680.0f
#define NBPI 13
#define HBINS 4096
#define LO_OBJ 0xBF19999Au   /* fmap(0.6f) */
#define LO_SCR 0xBF000000u   /* fmap(0.5f), 2^11-aligned */

// ---- device scratch (zero-init at load; self-cleaning across replays) ----
__device__ uint32_t g_mobj[BIMG * NBOX];
__device__ uint32_t g_hist[BIMG * HBINS];
__device__ uint32_t g_bndov[BIMG * NBOX];
__device__ uint16_t g_cand[BIMG * KSEL];
__device__ uint64_t g_skey[BIMG * KSEL];     // (fmap(score)<<32)|mobj
__device__ uint32_t g_pay[BIMG * KSEL];      // (n<<12)|ci
__device__ float4   g_boxu[BIMG * KSEL];
__device__ float    g_clsu[BIMG * KSEL];

__device__ __forceinline__ uint32_t fmap(float f) {
    uint32_t u = __float_as_uint(f);
    return (u & 0x80000000u) ? ~u : (u | 0x80000000u);
}
__device__ __forceinline__ float funmap(uint32_t u) {
    u = (u & 0x80000000u) ? (u & 0x7FFFFFFFu) : ~u;
    return __uint_as_float(u);
}
__device__ __forceinline__ uint32_t obj_bin(uint32_t mo) {
    if (mo <= LO_OBJ) return 0u;
    uint32_t b = (mo - LO_OBJ) >> 11;
    return b > 4095u ? 4095u : b;
}

// ---- K1: mobj + fine histogram ----------------------------------------
__global__ __launch_bounds__(256) void hist_kernel(const float* __restrict__ x) {
    __shared__ uint32_t sh[HBINS];
    const int img = blockIdx.x / NBPI;
    const int blk = blockIdx.x % NBPI;
    const int tid = threadIdx.x;
    for (int b = tid; b < HBINS; b += 256) sh[b] = 0;
    __syncthreads();
    const int base = blk * 2048;
    float objv[8];
    int nn[8];
    #pragma unroll
    for (int i = 0; i < 8; ++i) {
        nn[i] = base + i * 256 + tid;
        objv[i] = (nn[i] < NBOX) ? __ldg(&x[((size_t)img * NBOX + nn[i]) * ROWST + 4]) : 0.0f;
    }
    #pragma unroll
    for (int i = 0; i < 8; ++i) {
        if (nn[i] < NBOX) {
            float m = objv[i] > CONF_TH ? objv[i] : -1.0f;
            uint32_t mo = fmap(m);
            g_mobj[(size_t)img * NBOX + nn[i]] = mo;
            atomicAdd(&sh[obj_bin(mo)], 1u);
        }
    }
    __syncthreads();
    for (int b = tid; b < HBINS; b += 256) {
        uint32_t c = sh[b];
        if (c) atomicAdd(&g_hist[img * HBINS + b], c);
    }
}

// ---- K2: threshold + partition + boundary radix (fused, per-image) -----
__global__ __launch_bounds__(1024) void select_kernel() {
    __shared__ uint32_t segsum[256];
    __shared__ int sB, sR;
    __shared__ uint64_t sbnd[4096];
    __shared__ uint32_t rhist[256];
    __shared__ uint64_t s_prefix;
    __shared__ int s_rem, s_nc, s_nb;
    const int img = blockIdx.x;
    const int tid = threadIdx.x;
    const int bs = 1024;
    const uint32_t* h = g_hist + img * HBINS;

    if (tid == 0) { s_nc = 0; s_nb = 0; }
    if (tid < 256) {
        uint32_t s = 0;
        #pragma unroll
        for (int j = 0; j < 16; ++j) s += h[4095 - 16 * tid - j];
        segsum[tid] = s;
    }
    __syncthreads();
    if (tid == 0) {
        int cum = 0, B = 0, r = KSEL;
        for (int t = 0; t < 256; ++t) {
            if (cum + (int)segsum[t] >= KSEL) {
                for (int j = 0; j < 16; ++j) {
                    int b = 4095 - 16 * t - j;
                    int c = (int)h[b];
                    if (cum + c >= KSEL) { B = b; r = KSEL - cum; break; }
                    cum += c;
                }
                break;
            }
            cum += (int)segsum[t];
        }
        sB = B; sR = r;
    }
    __syncthreads();
    const int B = sB;

    for (int n = tid; n < NBOX; n += bs) {
        uint32_t mo = g_mobj[(size_t)img * NBOX + n];
        int b = (int)obj_bin(mo);
        if (b > B) {
            int p = atomicAdd(&s_nc, 1);
            g_cand[img * KSEL + p] = (uint16_t)n;
        } else if (b == B) {
            int p = atomicAdd(&s_nb, 1);
            uint64_t key = ((uint64_t)mo << 32) | (uint32_t)(~(uint32_t)n);
            if (p < 4096) sbnd[p] = key;
            else g_bndov[(size_t)img * NBOX + (p - 4096)] = (uint32_t)key;
        }
    }
    __syncthreads();
    const int m = s_nb;
    const int r = sR;

    uint64_t T = 0;
    if (r < m) {
        if (tid == 0) { s_prefix = 0ULL; s_rem = r; }
        __syncthreads();
        for (int d = 7; d >= 0; --d) {
            if (tid < 256) rhist[tid] = 0;
            __syncthreads();
            const int shift = d * 8;
            const uint64_t hmask = (d == 7) ? 0ULL : ~(((uint64_t)1 << ((d + 1) * 8)) - 1ULL);
            const uint64_t pref = s_prefix;
            for (int j = tid; j < m; j += bs) {
                uint64_t k = (j < 4096) ? sbnd[j]
                    : ((sbnd[0] & 0xFFFFFFFF00000000ULL) |
                       (uint64_t)g_bndov[(size_t)img * NBOX + (j - 4096)]);
                if ((k & hmask) == pref) {
                    uint32_t bin = (uint32_t)(k >> shift) & 0xFFu;
                    unsigned am = __activemask();
                    unsigned mm = __match_any_sync(am, bin);
                    int leader = __ffs(mm) - 1;
                    if ((int)(tid & 31) == leader) atomicAdd(&rhist[bin], (uint32_t)__popc(mm));
                }
            }
            __syncthreads();
            if (tid == 0) {
                int rem = s_rem;
                int b = 255;
                for (; b > 0; --b) {
                    int c = (int)rhist[b];
                    if (rem <= c) break;
                    rem -= c;
                }
                s_prefix = pref | ((uint64_t)(uint32_t)b << shift);
                s_rem = rem;
            }
            __syncthreads();
        }
        T = s_prefix;
    }
    __syncthreads();
    for (int j = tid; j < m; j += bs) {
        uint64_t k = (j < 4096) ? sbnd[j]
            : ((sbnd[0] & 0xFFFFFFFF00000000ULL) |
               (uint64_t)g_bndov[(size_t)img * NBOX + (j - 4096)]);
        if (k >= T) {
            int pos = atomicAdd(&s_nc, 1);
            g_cand[img * KSEL + pos] = (uint16_t)(~(uint32_t)k);
        }
    }
    __syncthreads();
    for (int i = tid; i < HBINS; i += bs) g_hist[img * HBINS + i] = 0;
}

// ---- K3: full-chip score/argmax/box for selected rows ------------------
__global__ __launch_bounds__(256) void score_kernel(const float* __restrict__ x) {
    const int wid = threadIdx.x >> 5, lane = threadIdx.x & 31;
    const int cidx = blockIdx.x * 8 + wid;
    if (cidx >= BIMG * KSEL) return;
    const int img = cidx >> 12;
    const int ci = cidx & (KSEL - 1);
    const int n = g_cand[cidx];
    const float* R = x + ((size_t)img * NBOX + n) * ROWST;

    float obj = __ldg(&R[4]);
    float v0 = __ldg(&R[5 + lane]);
    float v1 = __ldg(&R[5 + 32 + lane]);
    float v2 = (lane < 16) ? __ldg(&R[5 + 64 + lane]) : -1.0f;
    float best = -1.0f; int bidx = NCLS;
    if (v0 > best) { best = v0; bidx = lane; }
    if (v1 > best) { best = v1; bidx = lane + 32; }
    if (v2 > best) { best = v2; bidx = lane + 64; }
    #pragma unroll
    for (int off = 16; off > 0; off >>= 1) {
        float ov = __shfl_down_sync(0xFFFFFFFFu, best, off);
        int   oi = __shfl_down_sync(0xFFFFFFFFu, bidx, off);
        if (ov > best || (ov == best && oi < bidx)) { best = ov; bidx = oi; }
    }
    if (lane == 0) {
        bool valid = obj > CONF_TH;
        float score = valid ? __fmul_rn(obj, best) : -1.0f;
        uint32_t mo = g_mobj[(size_t)img * NBOX + n];
        g_skey[cidx] = ((uint64_t)fmap(score) << 32) | (uint64_t)mo;
        g_pay[cidx] = ((uint32_t)n << 12) | (uint32_t)ci;
        float cx = __ldg(&R[0]), cy = __ldg(&R[1]), w = __ldg(&R[2]), h = __ldg(&R[3]);
        float hw = __fmul_rn(w, 0.5f), hh = __fmul_rn(h, 0.5f);
        g_boxu[cidx] = make_float4(__fsub_rn(cx, hw), __fsub_rn(cy, hh),
                                   __fadd_rn(cx, hw), __fadd_rn(cy, hh));
        g_clsu[cidx] = (float)bidx;
    }
}

// digit p of the 96-bit key (H=fmap(score), M=mobj, L=~pay), MSD order.
__device__ __forceinline__ uint32_t sn_digit(uint64_t k, uint32_t pay, int p) {
    uint32_t H = (uint32_t)(k >> 32);
    uint32_t M = (uint32_t)k;
    uint32_t L = ~pay;
    switch (p) {
    case 0: { if (H <= LO_SCR) return 0u;
              uint32_t b = (H - LO_SCR) >> 11; return b > 4095u ? 4095u : b; }
    case 1: return H >> 20;
    case 2: return (H >> 8) & 0xFFFu;
    case 3: return ((H & 0xFFu) << 4) | (M >> 28);
    case 4: return (M >> 16) & 0xFFFu;
    case 5: return (M >> 4) & 0xFFFu;
    case 6: return ((M & 0xFu) << 8) | (L >> 24);
    case 7: return (L >> 12) & 0xFFFu;
    default: return L & 0xFFFu;
    }
}
__device__ __forceinline__ int key_gt(uint32_t aH, uint32_t aM, uint32_t aL,
                                      uint32_t bH2, uint32_t bM2, uint32_t bL2) {
    if (aH != bH2) return aH > bH2;
    if (aM != bM2) return aM > bM2;
    return aL > bL2;
}

__device__ __forceinline__ int iou_gt(float4 a, float4 b) {
    float lx = fmaxf(a.x, b.x), ly = fmaxf(a.y, b.y);
    float rx = fminf(a.z, b.z), ry = fminf(a.w, b.w);
    float iw = fmaxf(__fsub_rn(rx, lx), 0.0f);
    float ih = fmaxf(__fsub_rn(ry, ly), 0.0f);
    float inter = __fmul_rn(iw, ih);
    float aa = __fmul_rn(__fsub_rn(a.z, a.x), __fsub_rn(a.w, a.y));
    float ab = __fmul_rn(__fsub_rn(b.z, b.x), __fsub_rn(b.w, b.y));
    float denom = __fadd_rn(__fsub_rn(__fadd_rn(aa, ab), inter), 1e-9f);
    return __fdiv_rn(inter, denom) > IOU_T;
}

// ---- K4: fused top-PSEL select + sort + fixed-point NMS ----------------
__global__ __launch_bounds__(1024) void sortnms_kernel(float* __restrict__ out,
                                                       float* __restrict__ outvalid,
                                                       int write_valid) {
    __shared__ __align__(16) uint8_t scratch[16384];   // A: hist; B: kept/kcls/pm16
    __shared__ uint64_t sk[PSEL];
    __shared__ uint32_t sp[PSEL];
    __shared__ uint32_t segsum[256];
    __shared__ uint32_t bHh[256], bMm[256], bLl[256];
    __shared__ int bSel[256];
    __shared__ int sD, sRem, sMb, sBcnt, sCnt;
    __shared__ uint32_t rwH[32], rwM[32], rwL[32];
    __shared__ uint32_t sbH, sbM, sbL;
    __shared__ float4 cob[CHUNK], corig[CHUNK];
    __shared__ float cscore[CHUNK], ccls[CHUNK];
    __shared__ uint32_t sswW[4], Kw[4], Sw[4];
    __shared__ int s_k, sChanged;

    const int img = blockIdx.x;
    const int tid = threadIdx.x;
    const int wid = tid >> 5, lane = tid & 31;
    uint32_t* hist = (uint32_t*)scratch;

    // ---- Phase A: exact top-PSEL selection (register-resident keys) ----
    uint64_t rk[4]; uint32_t rp[4];
    bool act[4], sel[4];
    int bpos[4];
    #pragma unroll
    for (int q = 0; q < 4; ++q) {
        int i = tid + q * 1024;
        rk[q] = g_skey[img * KSEL + i];
        rp[q] = g_pay[img * KSEL + i];
        act[q] = true; sel[q] = false; bpos[q] = -1;
    }
    if (tid == 0) { sRem = PSEL; sBcnt = 0; sCnt = 0; }
    __syncthreads();

    bool done = false;
    for (int p = 0; p < 9 && !done; ++p) {
        for (int i = tid; i < 4096; i += 1024) hist[i] = 0;
        __syncthreads();
        #pragma unroll
        for (int q = 0; q < 4; ++q) {
            if (act[q]) {
                uint32_t d = sn_digit(rk[q], rp[q], p);
                unsigned am = __activemask();
                unsigned mm = __match_any_sync(am, d);
                int leader = __ffs(mm) - 1;
                if ((int)(tid & 31) == leader) atomicAdd(&hist[d], (uint32_t)__popc(mm));
            }
        }
        __syncthreads();
        if (tid < 256) {
            uint32_t s = 0;
            #pragma unroll
            for (int j = 0; j < 16; ++j) s += hist[4095 - 16 * tid - j];
            segsum[tid] = s;
        }
        __syncthreads();
        if (tid == 0) {
            int rem = sRem;
            int cum = 0, D = 0, r2 = rem;
            for (int t = 0; t < 256; ++t) {
                if (cum + (int)segsum[t] >= rem) {
                    for (int j = 0; j < 16; ++j) {
                        int b = 4095 - 16 * t - j;
                        int c = (int)hist[b];
                        if (cum + c >= rem) { D = b; r2 = rem - cum; break; }
                        cum += c;
                    }
                    break;
                }
                cum += (int)segsum[t];
            }
            sD = D; sRem = r2; sMb = (int)hist[D];
        }
        __syncthreads();
        const uint32_t D = (uint32_t)sD;
        const int rem2 = sRem, mb = sMb;
        #pragma unroll
        for (int q = 0; q < 4; ++q) {
            if (act[q]) {
                uint32_t d = sn_digit(rk[q], rp[q], p);
                if (d > D) { sel[q] = true; act[q] = false; }
                else if (d < D) act[q] = false;
            }
        }
        if (rem2 == mb) {
            #pragma unroll
            for (int q = 0; q < 4; ++q) if (act[q]) { sel[q] = true; act[q] = false; }
            done = true;
        } else if (mb <= 256) {
            #pragma unroll
            for (int q = 0; q < 4; ++q) {
                if (act[q]) {
                    int pos = atomicAdd(&sBcnt, 1);
                    bHh[pos] = (uint32_t)(rk[q] >> 32);
                    bMm[pos] = (uint32_t)rk[q];
                    bLl[pos] = ~rp[q];
                    bpos[q] = pos;
                }
            }
            __syncthreads();
            int m = sBcnt;
            if (tid < m) {
                uint32_t mH = bHh[tid], mM = bMm[tid], mL = bLl[tid];
                int rank = 0;
                for (int j = 0; j < m; ++j)
                    rank += key_gt(bHh[j], bMm[j], bLl[j], mH, mM, mL);
                bSel[tid] = (rank < rem2);
            }
            __syncthreads();
            #pragma unroll
            for (int q = 0; q < 4; ++q)
                if (act[q]) { sel[q] = (bSel[bpos[q]] != 0); act[q] = false; }
            done = true;
        }
        __syncthreads();
    }

    // compact selected PSEL entries, then bitonic sort (key desc, pay asc)
    #pragma unroll
    for (int q = 0; q < 4; ++q) {
        if (sel[q]) {
            int p = atomicAdd(&sCnt, 1);
            sk[p] = rk[q]; sp[p] = rp[q];
        }
    }
    __syncthreads();
    for (unsigned kk = 2; kk <= PSEL; kk <<= 1) {
        for (unsigned j = kk >> 1; j > 0; j >>= 1) {
            if (j >= 16) __syncthreads(); else __syncwarp();
            unsigned i = tid;
            unsigned ixj = i ^ j;
            if (ixj > i) {
                uint64_t a = sk[i], b = sk[ixj];
                uint32_t pa = sp[i], pb = sp[ixj];
                bool gt_i = (a > b) || (a == b && pa < pb);
                bool desc = ((i & kk) == 0);
                if (gt_i != desc) { sk[i] = b; sk[ixj] = a; sp[i] = pb; sp[ixj] = pa; }
            }
        }
    }
    __syncthreads();

    // ---- Phase B: chunked greedy NMS via monotone fixed-point ----
    float4* kept = (float4*)scratch;                         // 4800 B
    float*  kcls = (float*)(scratch + 4800);                 // 1200 B
    uint16_t (*pm16)[8] = (uint16_t(*)[8])(scratch + 6016);  // 2048 B
    if (tid == 0) s_k = 0;
    __syncthreads();

    bool truncated = false;
    for (int cb = 0; cb < NCHUNK; ++cb) {
        const int base = cb * CHUNK;
        float s = -1.0f;
        if (tid < CHUNK) {
            s = funmap((uint32_t)(sk[base + tid] >> 32));
            int ci = (int)(sp[base + tid] & (KSEL - 1));
            float4 b = g_boxu[img * KSEL + ci];
            float clsv = g_clsu[img * KSEL + ci];
            float off = __fmul_rn(clsv, MAXWH);
            cob[tid] = make_float4(__fadd_rn(b.x, off), __fadd_rn(b.y, off),
                                   __fadd_rn(b.z, off), __fadd_rn(b.w, off));
            corig[tid] = b;
            cscore[tid] = s;
            ccls[tid] = clsv;
        }
        if (tid < 4) sswW[tid] = 0;
        int nv = __syncthreads_count(tid < CHUNK && s > 0.0f);
        if (nv == 0) { truncated = true; break; }

        // kept-box suppression: 8 slices per candidate (sparse atomicOr)
        {
            int i = tid & (CHUNK - 1), slice = tid >> 7;
            float4 ob = cob[i];
            float clsv = ccls[i];
            int kc = s_k;
            int sup = 0;
            for (int t = slice; t < kc; t += 8)
                if (kcls[t] == clsv && iou_gt(ob, kept[t])) sup = 1;
            if (sup) atomicOr(&sswW[i >> 5], 1u << (i & 31));
        }
        // symmetric pairwise matrix: thread = (row, 16-col slice)
        {
            int row = tid & (CHUNK - 1), part = tid >> 7;
            float4 ob = cob[row];
            float clsv = ccls[row];
            uint32_t w = 0;
            int j0 = part * 16;
            #pragma unroll
            for (int jj = 0; jj < 16; ++jj) {
                int j = j0 + jj;
                int bit = (ccls[j] == clsv) ? iou_gt(ob, cob[j]) : 0;
                w |= (uint32_t)bit << jj;
            }
            pm16[row][part] = (uint16_t)w;
        }
        __syncthreads();

        // strictly-lower edge mask in registers (symmetric matrix => row=col)
        uint32_t e0 = 0, e1 = 0, e2 = 0, e3 = 0;
        bool det = true;
        if (tid < CHUNK) {
            uint32_t m0 = (uint32_t)pm16[tid][0] | ((uint32_t)pm16[tid][1] << 16);
            uint32_t m1 = (uint32_t)pm16[tid][2] | ((uint32_t)pm16[tid][3] << 16);
            uint32_t m2 = (uint32_t)pm16[tid][4] | ((uint32_t)pm16[tid][5] << 16);
            uint32_t m3 = (uint32_t)pm16[tid][6] | ((uint32_t)pm16[tid][7] << 16);
            int wd = tid >> 5, ln = tid & 31;
            uint32_t lm = (1u << ln) - 1u;
            e0 = (wd > 0) ? m0 : (m0 & lm);
            e1 = (wd > 1) ? m1 : ((wd == 1) ? (m1 & lm) : 0u);
            e2 = (wd > 2) ? m2 : ((wd == 2) ? (m2 & lm) : 0u);
            e3 = (wd == 3) ? (m3 & lm) : 0u;
        }
        if (tid < 4) {
            // invalid tail bits (index >= nv) are determined-suppressed
            int lo = tid * 32;
            uint32_t inv = (nv <= lo) ? ~0u : ((nv >= lo + 32) ? 0u : (~0u << (nv - lo)));
            Kw[tid] = 0u;
            Sw[tid] = sswW[tid] | inv;
        }
        __syncthreads();
        if (tid < CHUNK) det = ((Sw[tid >> 5] >> (tid & 31)) & 1u) != 0;

        // monotone fixed-point: exact greedy, converges in ~2 iters (sparse edges)
        for (;;) {
            if (tid == 0) sChanged = 0;
            __syncthreads();
            bool nK = false, nS = false;
            if (tid < CHUNK && !det) {
                uint32_t K0 = Kw[0], K1 = Kw[1], K2 = Kw[2], K3 = Kw[3];
                uint32_t S0 = Sw[0], S1 = Sw[1], S2 = Sw[2], S3 = Sw[3];
                uint32_t eK = (e0 & K0) | (e1 & K1) | (e2 & K2) | (e3 & K3);
                uint32_t eU = (e0 & ~(K0 | S0)) | (e1 & ~(K1 | S1)) |
                              (e2 & ~(K2 | S2)) | (e3 & ~(K3 | S3));
                if (eK) { nS = true; det = true; }
                else if (!eU) { nK = true; det = true; }
            }
            uint32_t bK = __ballot_sync(0xFFFFFFFFu, nK);
            uint32_t bS = __ballot_sync(0xFFFFFFFFu, nS);
            if (tid < CHUNK && lane == 0) {
                if (bK) Kw[wid] |= bK;
                if (bS) Sw[wid] |= bS;
                if (bK | bS) sChanged = 1;
            }
            __syncthreads();
            if (!sChanged) break;
        }

        // truncated append by popc-rank
        uint32_t K0 = Kw[0], K1 = Kw[1], K2 = Kw[2], K3 = Kw[3];
        int total = __popc(K0) + __popc(K1) + __popc(K2) + __popc(K3);
        int budget = MAXDET - s_k;
        int take = total < budget ? total : budget;
        if (tid < CHUNK && ((Kw[tid >> 5] >> (tid & 31)) & 1u)) {
            int wd = tid >> 5, ln = tid & 31;
            int rank = 0;
            if (wd > 0) rank += __popc(K0);
            if (wd > 1) rank += __popc(K1);
            if (wd > 2) rank += __popc(K2);
            rank += __popc(Kw[wd] & ((1u << ln) - 1u));
            if (rank < take) {
                int kpos = s_k + rank;
                kept[kpos] = cob[tid];
                kcls[kpos] = ccls[tid];
                float4 orig = corig[tid];
                float* orow = out + ((size_t)img * MAXDET + kpos) * 6;
                orow[0] = orig.x; orow[1] = orig.y; orow[2] = orig.z; orow[3] = orig.w;
                orow[4] = cscore[tid]; orow[5] = ccls[tid];
                if (write_valid) outvalid[(size_t)img * MAXDET + kpos] = 1.0f;
            }
        }
        __syncthreads();
        if (tid == 0) s_k += take;
        __syncthreads();
        if (s_k >= MAXDET) break;
        if (nv < CHUNK) { truncated = true; break; }
    }
    __syncthreads();

    // exact fallback beyond the prefix (register-resident; dead on typical data)
    if (!truncated && s_k < MAXDET) {
        bool used[4];
        #pragma unroll
        for (int q = 0; q < 4; ++q) used[q] = sel[q];
        while (true) {
            uint32_t hH = 0, hM = 0, hL = 0;
            #pragma unroll
            for (int q = 0; q < 4; ++q) {
                if (!used[q]) {
                    uint32_t H = (uint32_t)(rk[q] >> 32), M = (uint32_t)rk[q], L = ~rp[q];
                    if (key_gt(H, M, L, hH, hM, hL)) { hH = H; hM = M; hL = L; }
                }
            }
            #pragma unroll
            for (int o = 16; o > 0; o >>= 1) {
                uint32_t oH = __shfl_down_sync(0xFFFFFFFFu, hH, o);
                uint32_t oM = __shfl_down_sync(0xFFFFFFFFu, hM, o);
                uint32_t oL = __shfl_down_sync(0xFFFFFFFFu, hL, o);
                if (key_gt(oH, oM, oL, hH, hM, hL)) { hH = oH; hM = oM; hL = oL; }
            }
            if (lane == 0) { rwH[wid] = hH; rwM[wid] = hM; rwL[wid] = hL; }
            __syncthreads();
            if (wid == 0) {
                hH = rwH[lane]; hM = rwM[lane]; hL = rwL[lane];
                #pragma unroll
                for (int o = 16; o > 0; o >>= 1) {
                    uint32_t oH = __shfl_down_sync(0xFFFFFFFFu, hH, o);
                    uint32_t oM = __shfl_down_sync(0xFFFFFFFFu, hM, o);
                    uint32_t oL = __shfl_down_sync(0xFFFFFFFFu, hL, o);
                    if (key_gt(oH, oM, oL, hH, hM, hL)) { hH = oH; hM = oM; hL = oL; }
                }
                if (lane == 0) { sbH = hH; sbM = hM; sbL = hL; }
            }
            __syncthreads();
            uint32_t BH = sbH, BM = sbM, BL = sbL;
            float s = funmap(BH);
            if (!(s > 0.0f)) break;
            int ci = (int)((~BL) & (KSEL - 1));
            float4 b = g_boxu[img * KSEL + ci];
            float clsv = g_clsu[img * KSEL + ci];
            float off = __fmul_rn(clsv, MAXWH);
            float4 ob = make_float4(__fadd_rn(b.x, off), __fadd_rn(b.y, off),
                                    __fadd_rn(b.z, off), __fadd_rn(b.w, off));
            int sup = 0;
            for (int t = tid; t < s_k; t += 1024)
                if (kcls[t] == clsv && iou_gt(ob, kept[t])) sup = 1;
            int any = __syncthreads_or(sup);
            if (!any && tid == 0) {
                int k = s_k;
                kept[k] = ob; kcls[k] = clsv;
                float* orow = out + ((size_t)img * MAXDET + k) * 6;
                orow[0] = b.x; orow[1] = b.y; orow[2] = b.z; orow[3] = b.w;
                orow[4] = s; orow[5] = clsv;
                if (write_valid) outvalid[(size_t)img * MAXDET + k] = 1.0f;
                s_k = k + 1;
            }
            #pragma unroll
            for (int q = 0; q < 4; ++q)
                if (!used[q] && (uint32_t)(rk[q] >> 32) == BH &&
                    (uint32_t)rk[q] == BM && (~rp[q]) == BL) used[q] = true;
            __syncthreads();
            if (s_k >= MAXDET) break;
        }
    }
    __syncthreads();
    int kc = s_k;
    for (int e = tid; e < (MAXDET - kc) * 6; e += 1024)
        out[(size_t)img * MAXDET * 6 + (size_t)kc * 6 + e] = 0.0f;
    if (write_valid)
        for (int r = kc + tid; r < MAXDET; r += 1024)
            outvalid[(size_t)img * MAXDET + r] = 0.0f;
}

extern "C" void kernel_launch(void* const* d_in, const int* in_sizes, int n_in,
                              void* d_out, int out_size) {
    const float* x = (const float*)d_in[0];
    float* out = (float*)d_out;
    int write_valid = (out_size >= BIMG * MAXDET * 7) ? 1 : 0;
    float* outvalid = out + (size_t)BIMG * MAXDET * 6;
    hist_kernel<<<BIMG * NBPI, 256>>>(x);
    select_kernel<<<BIMG, 1024>>>();
    score_kernel<<<(BIMG * KSEL + 7) / 8, 256>>>(x);
    sortnms_kernel<<<BIMG, 1024>>>(out, outvalid, write_valid);
}